// round 6
// baseline (speedup 1.0000x reference)
#include <cuda_runtime.h>
#include <cuda_bf16.h>
#include <cuda_fp8.h>
#include <cstdint>
#include <cstddef>

#define FP8_MAX 448.0f

// ---------------- scratch (device globals; no runtime allocation) -------------
static __device__ __align__(16) __nv_bfloat16 g_x_bf16[(size_t)32768 * 1024];
static __device__ __align__(16) __nv_bfloat16 g_w_bf16[(size_t)1024 * 1024];
static __device__ float g_part[1024];
static __device__ float g_amax;

__device__ __forceinline__ float bf16r(float v) {
    return __bfloat162float(__float2bfloat16(v));
}

// ---------------- PTX helpers -------------------------------------------------
__device__ __forceinline__ uint32_t smem_u32(const void* p) {
    uint32_t a;
    asm("{ .reg .u64 t; cvta.to.shared.u64 t, %1; cvt.u32.u64 %0, t; }"
        : "=r"(a) : "l"(p));
    return a;
}
__device__ __forceinline__ void cp_async16(uint32_t dst, const void* src) {
    asm volatile("cp.async.cg.shared.global [%0], [%1], 16;\n" :: "r"(dst), "l"(src));
}
__device__ __forceinline__ void cp_commit() {
    asm volatile("cp.async.commit_group;\n" ::: "memory");
}
template <int N>
__device__ __forceinline__ void cp_wait() {
    asm volatile("cp.async.wait_group %0;\n" :: "n"(N) : "memory");
}
__device__ __forceinline__ uint32_t lds32(uint32_t addr) {
    uint32_t v;
    asm volatile("ld.shared.b32 %0, [%1];" : "=r"(v) : "r"(addr));
    return v;
}
__device__ __forceinline__ void mma_bf16(float* c, const uint32_t* a, const uint32_t* b) {
    asm volatile(
        "mma.sync.aligned.m16n8k16.row.col.f32.bf16.bf16.f32 "
        "{%0,%1,%2,%3}, {%4,%5,%6,%7}, {%8,%9}, {%0,%1,%2,%3};"
        : "+f"(c[0]), "+f"(c[1]), "+f"(c[2]), "+f"(c[3])
        : "r"(a[0]), "r"(a[1]), "r"(a[2]), "r"(a[3]), "r"(b[0]), "r"(b[1]));
}

// ---------------- deterministic two-pass amax -----------------------------------
__global__ void k_amax1(const float* __restrict__ x, int n) {
    __shared__ float sm[256];
    float m = 0.0f;
    for (int j = blockIdx.x * blockDim.x + threadIdx.x; j < n;
         j += gridDim.x * blockDim.x)
        m = fmaxf(m, fabsf(bf16r(x[j])));
    sm[threadIdx.x] = m;
    __syncthreads();
#pragma unroll
    for (int o = 128; o > 0; o >>= 1) {
        if (threadIdx.x < o) sm[threadIdx.x] = fmaxf(sm[threadIdx.x], sm[threadIdx.x + o]);
        __syncthreads();
    }
    if (threadIdx.x == 0) g_part[blockIdx.x] = sm[0];
}
__global__ void k_amax2() {
    __shared__ float sm[1024];
    sm[threadIdx.x] = g_part[threadIdx.x];
    __syncthreads();
#pragma unroll
    for (int o = 512; o > 0; o >>= 1) {
        if (threadIdx.x < o) sm[threadIdx.x] = fmaxf(sm[threadIdx.x], sm[threadIdx.x + o]);
        __syncthreads();
    }
    if (threadIdx.x == 0) g_amax = fmaxf(sm[0], 1e-12f);
}

// ---------------- staging quant -------------------------------------------------
// x: f32 -> bf16-round -> /s -> e4m3 grid (RN satfinite) -> exact in bf16
__global__ void k_quant_x(const float* __restrict__ x, int n) {
    float s = g_amax / FP8_MAX;
    int i = blockIdx.x * blockDim.x + threadIdx.x;
    int stride = gridDim.x * blockDim.x;
    const float4* x4 = (const float4*)x;
    __nv_bfloat162* d2 = (__nv_bfloat162*)g_x_bf16;
    int n4 = n >> 2;
    for (int j = i; j < n4; j += stride) {
        float4 v = x4[j];
        float q0 = (float)__nv_fp8_e4m3(bf16r(v.x) / s);
        float q1 = (float)__nv_fp8_e4m3(bf16r(v.y) / s);
        float q2 = (float)__nv_fp8_e4m3(bf16r(v.z) / s);
        float q3 = (float)__nv_fp8_e4m3(bf16r(v.w) / s);
        d2[2 * j]     = __floats2bfloat162_rn(q0, q1);
        d2[2 * j + 1] = __floats2bfloat162_rn(q2, q3);
    }
}
// w already holds exact e4m3 values in f32 containers -> exact cast to bf16
__global__ void k_quant_w(const float* __restrict__ w, int n) {
    int i = blockIdx.x * blockDim.x + threadIdx.x;
    int stride = gridDim.x * blockDim.x;
    const float4* w4 = (const float4*)w;
    __nv_bfloat162* d2 = (__nv_bfloat162*)g_w_bf16;
    int n4 = n >> 2;
    for (int j = i; j < n4; j += stride) {
        float4 v = w4[j];
        d2[2 * j]     = __floats2bfloat162_rn(v.x, v.y);
        d2[2 * j + 1] = __floats2bfloat162_rn(v.z, v.w);
    }
}

// ---------------- bf16 HMMA GEMM (direct-LDS fragments, 2-stage cp.async) -------
#define BM 128
#define BN 128
#define BK 32
#define ROWB 80                          // 64 data bytes + 16 pad per row
#define OPB (128 * ROWB)                 // 10240 per operand tile
#define STB (2 * OPB)                    // 20480 per stage
#define SMEM_GEMM_TOTAL (2 * STB)        // 40960 <= 48KB default

__global__ void __launch_bounds__(256)
k_gemm(const float* __restrict__ wscale,
       const float* __restrict__ bias,
       float* __restrict__ out,          // f32 container, bf16-rounded values
       int M, int N, int K)
{
    extern __shared__ __align__(128) uint8_t smem[];
    const uint32_t sbase = smem_u32(smem);
    const int tid = threadIdx.x;
    const int wid = tid >> 5;
    const int lane = tid & 31;
    const int g = lane >> 2;             // groupID
    const int t = lane & 3;              // threadID_in_group
    const int warp_m = wid & 3;          // 4 warps along M
    const int warp_n = wid >> 2;         // 2 warps along N
    const int wm = warp_m * 32;          // warp tile 32(M) x 64(N)
    const int wn = warp_n * 64;
    const int m0 = blockIdx.y * BM;
    const int n0 = blockIdx.x * BN;
    const __nv_bfloat16* __restrict__ A = g_x_bf16;
    const __nv_bfloat16* __restrict__ B = g_w_bf16;
    const int NK = K / BK;               // 32

    auto load_chunk = [&](int kt, int buf) {
        uint32_t abase = sbase + buf * STB;
        uint32_t bbase = abase + OPB;
        const __nv_bfloat16* a_src = A + (size_t)m0 * K + kt * BK;
        const __nv_bfloat16* b_src = B + (size_t)n0 * K + kt * BK;
#pragma unroll
        for (int j = 0; j < 2; j++) {
            int id = tid + j * 256;      // 0..511 -> (row, 16B-chunk)
            int row = id >> 2;
            int cc = id & 3;
            uint32_t soff = (uint32_t)(row * ROWB + cc * 16);
            cp_async16(abase + soff, (const uint8_t*)(a_src + (size_t)row * K) + cc * 16);
            cp_async16(bbase + soff, (const uint8_t*)(b_src + (size_t)row * K) + cc * 16);
        }
    };

    float c[2][8][4];
#pragma unroll
    for (int i = 0; i < 2; i++)
#pragma unroll
        for (int j = 0; j < 8; j++)
#pragma unroll
            for (int q = 0; q < 4; q++) c[i][j][q] = 0.0f;

    load_chunk(0, 0);
    cp_commit();

    for (int i = 0; i < NK; i++) {
        // issue next chunk's loads first so they overlap chunk i's compute
        if (i + 1 < NK) {
            load_chunk(i + 1, (i + 1) & 1);
            cp_commit();
            cp_wait<1>();                // chunk i resident; chunk i+1 in flight
        } else {
            cp_wait<0>();
        }
        __syncthreads();

        uint32_t abase = sbase + (uint32_t)(i & 1) * STB;
        uint32_t bbase = abase + OPB;

#pragma unroll
        for (int ks = 0; ks < 2; ks++) {
            uint32_t af[2][4];
#pragma unroll
            for (int ti = 0; ti < 2; ti++) {
                uint32_t r0 = abase + (uint32_t)((wm + ti * 16 + g) * ROWB + (ks * 16 + 2 * t) * 2);
                af[ti][0] = lds32(r0);
                af[ti][1] = lds32(r0 + 8 * ROWB);
                af[ti][2] = lds32(r0 + 16);
                af[ti][3] = lds32(r0 + 8 * ROWB + 16);
            }
            uint32_t bf[8][2];
#pragma unroll
            for (int tj = 0; tj < 8; tj++) {
                uint32_t rb = bbase + (uint32_t)((wn + tj * 8 + g) * ROWB + (ks * 16 + 2 * t) * 2);
                bf[tj][0] = lds32(rb);
                bf[tj][1] = lds32(rb + 16);
            }
#pragma unroll
            for (int ti = 0; ti < 2; ti++)
#pragma unroll
                for (int tj = 0; tj < 8; tj++)
                    mma_bf16(c[ti][tj], af[ti], bf[tj]);
        }
        __syncthreads();                 // reads of buf i&1 done before its refill
    }

    // epilogue: f32 out, values rounded to bf16 grid (matches .astype(bf16))
    float act_scale = g_amax / FP8_MAX;
    const int row_b = m0 + wm + g;
    const int col_b = wn + 2 * t;
#pragma unroll
    for (int ti = 0; ti < 2; ti++) {
#pragma unroll
        for (int tj = 0; tj < 8; tj++) {
            int col = n0 + col_b + 8 * tj;
            float s0 = act_scale * __ldg(&wscale[col]);
            float s1 = act_scale * __ldg(&wscale[col + 1]);
            float b0 = __ldg(&bias[col]);
            float b1 = __ldg(&bias[col + 1]);
            int r0 = row_b + 16 * ti;
            int r1 = r0 + 8;
            float2 h0 = make_float2(bf16r(fmaf(c[ti][tj][0], s0, b0)),
                                    bf16r(fmaf(c[ti][tj][1], s1, b1)));
            float2 h1 = make_float2(bf16r(fmaf(c[ti][tj][2], s0, b0)),
                                    bf16r(fmaf(c[ti][tj][3], s1, b1)));
            *(float2*)(out + (size_t)r0 * N + col) = h0;
            *(float2*)(out + (size_t)r1 * N + col) = h1;
        }
    }
}

// ---------------- launch --------------------------------------------------------
extern "C" void kernel_launch(void* const* d_in, const int* in_sizes, int n_in,
                              void* d_out, int out_size) {
    const float* x  = (const float*)d_in[0];
    const float* w  = (const float*)d_in[1];
    const float* ws = (const float*)d_in[2];
    const float* b  = (const float*)d_in[3];
    float* out = (float*)d_out;                  // f32 container (numpy has no bf16)

    int d_out_dim = in_sizes[2];                 // 1024
    int d_in_dim  = in_sizes[1] / d_out_dim;     // 1024
    int tokens    = in_sizes[0] / d_in_dim;      // 32768
    int nx = in_sizes[0];
    int nw = in_sizes[1];

    k_amax1<<<1024, 256>>>(x, nx);
    k_amax2<<<1, 1024>>>();
    k_quant_x<<<2048, 256>>>(x, nx);
    k_quant_w<<<512, 256>>>(w, nw);

    dim3 grid(d_out_dim / BN, tokens / BM);      // N-tiles fastest -> A-tile L2 reuse
    k_gemm<<<grid, 256, SMEM_GEMM_TOTAL>>>(ws, b, out, tokens, d_out_dim, d_in_dim);
}

// round 7
// speedup vs baseline: 1.1246x; 1.1246x over previous
#include <cuda_runtime.h>
#include <cuda_bf16.h>
#include <cuda_fp8.h>
#include <cstdint>
#include <cstddef>

#define FP8_MAX 448.0f

// ---------------- scratch (device globals; no runtime allocation) -------------
static __device__ __align__(16) uint8_t g_x_fp8[(size_t)32768 * 1024];
static __device__ __align__(16) uint8_t g_w_fp8[(size_t)1024 * 1024];
static __device__ float g_part[1024];
static __device__ float g_amax;

__device__ __forceinline__ float bf16r(float v) {
    return __bfloat162float(__float2bfloat16(v));
}

// ---------------- PTX helpers -------------------------------------------------
__device__ __forceinline__ uint32_t smem_u32(const void* p) {
    uint32_t a;
    asm("{ .reg .u64 t; cvta.to.shared.u64 t, %1; cvt.u32.u64 %0, t; }"
        : "=r"(a) : "l"(p));
    return a;
}
__device__ __forceinline__ void cp_async16(uint32_t dst, const void* src) {
    asm volatile("cp.async.cg.shared.global [%0], [%1], 16;\n" :: "r"(dst), "l"(src));
}
__device__ __forceinline__ void cp_commit() {
    asm volatile("cp.async.commit_group;\n" ::: "memory");
}
template <int N>
__device__ __forceinline__ void cp_wait() {
    asm volatile("cp.async.wait_group %0;\n" :: "n"(N) : "memory");
}
__device__ __forceinline__ uint32_t lds32(uint32_t addr) {
    uint32_t v;
    asm volatile("ld.shared.b32 %0, [%1];" : "=r"(v) : "r"(addr));
    return v;
}
// fp8 e4m3 MMA: D(16x8,f32) += A(16x32,e4m3) * B(32x8,e4m3)
__device__ __forceinline__ void mma_fp8(float* c, const uint32_t* a, const uint32_t* b) {
    asm volatile(
        "mma.sync.aligned.m16n8k32.row.col.f32.e4m3.e4m3.f32 "
        "{%0,%1,%2,%3}, {%4,%5,%6,%7}, {%8,%9}, {%0,%1,%2,%3};"
        : "+f"(c[0]), "+f"(c[1]), "+f"(c[2]), "+f"(c[3])
        : "r"(a[0]), "r"(a[1]), "r"(a[2]), "r"(a[3]), "r"(b[0]), "r"(b[1]));
}

// ---------------- deterministic two-pass amax -----------------------------------
__global__ void k_amax1(const float* __restrict__ x, int n) {
    __shared__ float sm[256];
    float m = 0.0f;
    const float4* x4 = (const float4*)x;
    int n4 = n >> 2;
    for (int j = blockIdx.x * blockDim.x + threadIdx.x; j < n4;
         j += gridDim.x * blockDim.x) {
        float4 v = x4[j];
        m = fmaxf(m, fabsf(bf16r(v.x)));
        m = fmaxf(m, fabsf(bf16r(v.y)));
        m = fmaxf(m, fabsf(bf16r(v.z)));
        m = fmaxf(m, fabsf(bf16r(v.w)));
    }
    sm[threadIdx.x] = m;
    __syncthreads();
#pragma unroll
    for (int o = 128; o > 0; o >>= 1) {
        if (threadIdx.x < o) sm[threadIdx.x] = fmaxf(sm[threadIdx.x], sm[threadIdx.x + o]);
        __syncthreads();
    }
    if (threadIdx.x == 0) g_part[blockIdx.x] = sm[0];
}
__global__ void k_amax2() {
    __shared__ float sm[1024];
    sm[threadIdx.x] = g_part[threadIdx.x];
    __syncthreads();
#pragma unroll
    for (int o = 512; o > 0; o >>= 1) {
        if (threadIdx.x < o) sm[threadIdx.x] = fmaxf(sm[threadIdx.x], sm[threadIdx.x + o]);
        __syncthreads();
    }
    if (threadIdx.x == 0) g_amax = fmaxf(sm[0], 1e-12f);
}

// ---------------- staging quant (to fp8 bytes) -----------------------------------
__global__ void k_quant_x(const float* __restrict__ x, int n) {
    float s = g_amax / FP8_MAX;
    int i = blockIdx.x * blockDim.x + threadIdx.x;
    int stride = gridDim.x * blockDim.x;
    const float4* x4 = (const float4*)x;
    uchar4* d4 = (uchar4*)g_x_fp8;
    int n4 = n >> 2;
    for (int j = i; j < n4; j += stride) {
        float4 v = x4[j];
        uchar4 q;
        q.x = __nv_fp8_e4m3(bf16r(v.x) / s).__x;
        q.y = __nv_fp8_e4m3(bf16r(v.y) / s).__x;
        q.z = __nv_fp8_e4m3(bf16r(v.z) / s).__x;
        q.w = __nv_fp8_e4m3(bf16r(v.w) / s).__x;
        d4[j] = q;
    }
}
// w already holds exact e4m3 values in f32 containers -> exact re-encode to e4m3
__global__ void k_quant_w(const float* __restrict__ w, int n) {
    int i = blockIdx.x * blockDim.x + threadIdx.x;
    int stride = gridDim.x * blockDim.x;
    const float4* w4 = (const float4*)w;
    uchar4* d4 = (uchar4*)g_w_fp8;
    int n4 = n >> 2;
    for (int j = i; j < n4; j += stride) {
        float4 v = w4[j];
        uchar4 q;
        q.x = __nv_fp8_e4m3(v.x).__x;
        q.y = __nv_fp8_e4m3(v.y).__x;
        q.z = __nv_fp8_e4m3(v.z).__x;
        q.w = __nv_fp8_e4m3(v.w).__x;
        d4[j] = q;
    }
}

// ---------------- fp8 MMA GEMM (direct-LDS fragments, 2-stage cp.async) ---------
#define BM 128
#define BN 128
#define BK 64                            // 64 fp8 bytes of K per chunk
#define ROWB 80                          // 64 data bytes + 16 pad per row (16B-aligned)
#define OPB (128 * ROWB)                 // 10240 per operand tile
#define STB (2 * OPB)                    // 20480 per stage
#define SMEM_GEMM_TOTAL (2 * STB)        // 40960 <= 48KB default

__global__ void __launch_bounds__(256)
k_gemm(const float* __restrict__ wscale,
       const float* __restrict__ bias,
       float* __restrict__ out,          // f32 container, bf16-rounded values
       int M, int N, int K)
{
    extern __shared__ __align__(128) uint8_t smem[];
    const uint32_t sbase = smem_u32(smem);
    const int tid = threadIdx.x;
    const int wid = tid >> 5;
    const int lane = tid & 31;
    const int g = lane >> 2;             // groupID
    const int t = lane & 3;              // threadID_in_group
    const int warp_m = wid & 3;          // 4 warps along M
    const int warp_n = wid >> 2;         // 2 warps along N
    const int wm = warp_m * 32;          // warp tile 32(M) x 64(N)
    const int wn = warp_n * 64;
    const int m0 = blockIdx.y * BM;
    const int n0 = blockIdx.x * BN;
    const uint8_t* __restrict__ A = g_x_fp8;
    const uint8_t* __restrict__ B = g_w_fp8;
    const int NK = K / BK;               // 16

    auto load_chunk = [&](int kt, int buf) {
        uint32_t abase = sbase + buf * STB;
        uint32_t bbase = abase + OPB;
        const uint8_t* a_src = A + (size_t)m0 * K + kt * BK;
        const uint8_t* b_src = B + (size_t)n0 * K + kt * BK;
#pragma unroll
        for (int j = 0; j < 2; j++) {
            int id = tid + j * 256;      // 0..511 -> (row, 16B-chunk)
            int row = id >> 2;
            int cc = id & 3;
            uint32_t soff = (uint32_t)(row * ROWB + cc * 16);
            cp_async16(abase + soff, a_src + (size_t)row * K + cc * 16);
            cp_async16(bbase + soff, b_src + (size_t)row * K + cc * 16);
        }
    };

    float c[2][8][4];
#pragma unroll
    for (int i = 0; i < 2; i++)
#pragma unroll
        for (int j = 0; j < 8; j++)
#pragma unroll
            for (int q = 0; q < 4; q++) c[i][j][q] = 0.0f;

    load_chunk(0, 0);
    cp_commit();

    for (int i = 0; i < NK; i++) {
        if (i + 1 < NK) {                // overlap: issue i+1 before waiting on i
            load_chunk(i + 1, (i + 1) & 1);
            cp_commit();
            cp_wait<1>();
        } else {
            cp_wait<0>();
        }
        __syncthreads();

        uint32_t abase = sbase + (uint32_t)(i & 1) * STB;
        uint32_t bbase = abase + OPB;

#pragma unroll
        for (int ks = 0; ks < 2; ks++) {   // two k32 sub-steps per 64B chunk
            // A frags: a0=A[g][4t..4t+3], a1=A[g+8][..], a2=A[g][4t+16..], a3=A[g+8][4t+16..]
            uint32_t af[2][4];
#pragma unroll
            for (int ti = 0; ti < 2; ti++) {
                uint32_t r0 = abase + (uint32_t)((wm + ti * 16 + g) * ROWB + ks * 32 + 4 * t);
                af[ti][0] = lds32(r0);
                af[ti][1] = lds32(r0 + 8 * ROWB);
                af[ti][2] = lds32(r0 + 16);
                af[ti][3] = lds32(r0 + 8 * ROWB + 16);
            }
            // B frags: b0=B[n=g][4t..4t+3], b1=B[n=g][4t+16..4t+19]
            uint32_t bf[8][2];
#pragma unroll
            for (int tj = 0; tj < 8; tj++) {
                uint32_t rb = bbase + (uint32_t)((wn + tj * 8 + g) * ROWB + ks * 32 + 4 * t);
                bf[tj][0] = lds32(rb);
                bf[tj][1] = lds32(rb + 16);
            }
#pragma unroll
            for (int ti = 0; ti < 2; ti++)
#pragma unroll
                for (int tj = 0; tj < 8; tj++)
                    mma_fp8(c[ti][tj], af[ti], bf[tj]);
        }
        __syncthreads();                 // reads of buf i&1 done before its refill
    }

    // epilogue: f32 out, values rounded to bf16 grid (matches .astype(bf16))
    float act_scale = g_amax / FP8_MAX;
    const int row_b = m0 + wm + g;
    const int col_b = wn + 2 * t;
#pragma unroll
    for (int ti = 0; ti < 2; ti++) {
#pragma unroll
        for (int tj = 0; tj < 8; tj++) {
            int col = n0 + col_b + 8 * tj;
            float s0 = act_scale * __ldg(&wscale[col]);
            float s1 = act_scale * __ldg(&wscale[col + 1]);
            float b0 = __ldg(&bias[col]);
            float b1 = __ldg(&bias[col + 1]);
            int r0 = row_b + 16 * ti;
            int r1 = r0 + 8;
            float2 h0 = make_float2(bf16r(fmaf(c[ti][tj][0], s0, b0)),
                                    bf16r(fmaf(c[ti][tj][1], s1, b1)));
            float2 h1 = make_float2(bf16r(fmaf(c[ti][tj][2], s0, b0)),
                                    bf16r(fmaf(c[ti][tj][3], s1, b1)));
            *(float2*)(out + (size_t)r0 * N + col) = h0;
            *(float2*)(out + (size_t)r1 * N + col) = h1;
        }
    }
}

// ---------------- launch --------------------------------------------------------
extern "C" void kernel_launch(void* const* d_in, const int* in_sizes, int n_in,
                              void* d_out, int out_size) {
    const float* x  = (const float*)d_in[0];
    const float* w  = (const float*)d_in[1];
    const float* ws = (const float*)d_in[2];
    const float* b  = (const float*)d_in[3];
    float* out = (float*)d_out;                  // f32 container (numpy has no bf16)

    int d_out_dim = in_sizes[2];                 // 1024
    int d_in_dim  = in_sizes[1] / d_out_dim;     // 1024
    int tokens    = in_sizes[0] / d_in_dim;      // 32768
    int nx = in_sizes[0];
    int nw = in_sizes[1];

    k_amax1<<<1024, 256>>>(x, nx);
    k_amax2<<<1, 1024>>>();
    k_quant_x<<<2048, 256>>>(x, nx);
    k_quant_w<<<512, 256>>>(w, nw);

    dim3 grid(d_out_dim / BN, tokens / BM);      // N-tiles fastest -> A-tile L2 reuse
    k_gemm<<<grid, 256, SMEM_GEMM_TOTAL>>>(ws, b, out, tokens, d_out_dim, d_in_dim);
}

// round 8
// speedup vs baseline: 1.1747x; 1.0446x over previous
#include <cuda_runtime.h>
#include <cuda_bf16.h>
#include <cuda_fp8.h>
#include <cstdint>
#include <cstddef>

#define FP8_MAX 448.0f

// ---------------- scratch (device globals; no runtime allocation) -------------
static __device__ __align__(16) uint8_t g_x_fp8[(size_t)32768 * 1024];
static __device__ __align__(16) uint8_t g_w_fp8[(size_t)1024 * 1024];
static __device__ float g_part[1024];
static __device__ float g_amax;

__device__ __forceinline__ float bf16r(float v) {
    return __bfloat162float(__float2bfloat16(v));
}

// ---------------- PTX helpers -------------------------------------------------
__device__ __forceinline__ uint32_t smem_u32(const void* p) {
    uint32_t a;
    asm("{ .reg .u64 t; cvta.to.shared.u64 t, %1; cvt.u32.u64 %0, t; }"
        : "=r"(a) : "l"(p));
    return a;
}
__device__ __forceinline__ void cp_async16(uint32_t dst, const void* src) {
    asm volatile("cp.async.cg.shared.global [%0], [%1], 16;\n" :: "r"(dst), "l"(src));
}
__device__ __forceinline__ void cp_commit() {
    asm volatile("cp.async.commit_group;\n" ::: "memory");
}
template <int N>
__device__ __forceinline__ void cp_wait() {
    asm volatile("cp.async.wait_group %0;\n" :: "n"(N) : "memory");
}
__device__ __forceinline__ void ldmatrix_x4(uint32_t* r, uint32_t addr) {
    asm volatile("ldmatrix.sync.aligned.m8n8.x4.shared.b16 {%0,%1,%2,%3}, [%4];"
                 : "=r"(r[0]), "=r"(r[1]), "=r"(r[2]), "=r"(r[3]) : "r"(addr));
}
// fp8 e4m3 MMA: D(16x8,f32) += A(16x32,e4m3) * B(32x8,e4m3)
__device__ __forceinline__ void mma_fp8(float* c, const uint32_t* a, const uint32_t* b) {
    asm volatile(
        "mma.sync.aligned.m16n8k32.row.col.f32.e4m3.e4m3.f32 "
        "{%0,%1,%2,%3}, {%4,%5,%6,%7}, {%8,%9}, {%0,%1,%2,%3};"
        : "+f"(c[0]), "+f"(c[1]), "+f"(c[2]), "+f"(c[3])
        : "r"(a[0]), "r"(a[1]), "r"(a[2]), "r"(a[3]), "r"(b[0]), "r"(b[1]));
}

// ---------------- deterministic two-pass amax -----------------------------------
__global__ void k_amax1(const float* __restrict__ x, int n) {
    __shared__ float sm[256];
    float m = 0.0f;
    const float4* x4 = (const float4*)x;
    int n4 = n >> 2;
    for (int j = blockIdx.x * blockDim.x + threadIdx.x; j < n4;
         j += gridDim.x * blockDim.x) {
        float4 v = x4[j];
        m = fmaxf(m, fabsf(bf16r(v.x)));
        m = fmaxf(m, fabsf(bf16r(v.y)));
        m = fmaxf(m, fabsf(bf16r(v.z)));
        m = fmaxf(m, fabsf(bf16r(v.w)));
    }
    sm[threadIdx.x] = m;
    __syncthreads();
#pragma unroll
    for (int o = 128; o > 0; o >>= 1) {
        if (threadIdx.x < o) sm[threadIdx.x] = fmaxf(sm[threadIdx.x], sm[threadIdx.x + o]);
        __syncthreads();
    }
    if (threadIdx.x == 0) g_part[blockIdx.x] = sm[0];
}
__global__ void k_amax2() {
    __shared__ float sm[1024];
    sm[threadIdx.x] = g_part[threadIdx.x];
    __syncthreads();
#pragma unroll
    for (int o = 512; o > 0; o >>= 1) {
        if (threadIdx.x < o) sm[threadIdx.x] = fmaxf(sm[threadIdx.x], sm[threadIdx.x + o]);
        __syncthreads();
    }
    if (threadIdx.x == 0) g_amax = fmaxf(sm[0], 1e-12f);
}

// ---------------- staging quant (to fp8 bytes) -----------------------------------
__global__ void k_quant_x(const float* __restrict__ x, int n) {
    float s = g_amax / FP8_MAX;
    int i = blockIdx.x * blockDim.x + threadIdx.x;
    int stride = gridDim.x * blockDim.x;
    const float4* x4 = (const float4*)x;
    uchar4* d4 = (uchar4*)g_x_fp8;
    int n4 = n >> 2;
    for (int j = i; j < n4; j += stride) {
        float4 v = x4[j];
        uchar4 q;
        q.x = __nv_fp8_e4m3(bf16r(v.x) / s).__x;
        q.y = __nv_fp8_e4m3(bf16r(v.y) / s).__x;
        q.z = __nv_fp8_e4m3(bf16r(v.z) / s).__x;
        q.w = __nv_fp8_e4m3(bf16r(v.w) / s).__x;
        d4[j] = q;
    }
}
__global__ void k_quant_w(const float* __restrict__ w, int n) {
    int i = blockIdx.x * blockDim.x + threadIdx.x;
    int stride = gridDim.x * blockDim.x;
    const float4* w4 = (const float4*)w;
    uchar4* d4 = (uchar4*)g_w_fp8;
    int n4 = n >> 2;
    for (int j = i; j < n4; j += stride) {
        float4 v = w4[j];
        uchar4 q;
        q.x = __nv_fp8_e4m3(v.x).__x;
        q.y = __nv_fp8_e4m3(v.y).__x;
        q.z = __nv_fp8_e4m3(v.z).__x;
        q.w = __nv_fp8_e4m3(v.w).__x;
        d4[j] = q;
    }
}

// ---------------- fp8 MMA GEMM (ldmatrix fragments, 4-stage cp.async) -----------
#define BM 128
#define BN 128
#define BK 32                            // 32 fp8 bytes of K per chunk
#define ROWB 48                          // 32 data bytes + 16 pad (16B aligned rows)
#define OPB (128 * ROWB)                 // 6144 per operand tile
#define STB (2 * OPB)                    // 12288 per stage
#define STAGES 4
#define SMEM_GEMM_TOTAL (STAGES * STB)   // 49152 == default 48KB limit

__global__ void __launch_bounds__(256)
k_gemm(const float* __restrict__ wscale,
       const float* __restrict__ bias,
       float* __restrict__ out,          // f32 container, bf16-rounded values
       int M, int N, int K)
{
    extern __shared__ __align__(128) uint8_t smem[];
    const uint32_t sbase = smem_u32(smem);
    const int tid = threadIdx.x;
    const int wid = tid >> 5;
    const int lane = tid & 31;
    const int g = lane >> 2;             // groupID
    const int t = lane & 3;              // threadID_in_group
    const int warp_m = wid & 3;          // 4 warps along M
    const int warp_n = wid >> 2;         // 2 warps along N
    const int wm = warp_m * 32;          // warp tile 32(M) x 64(N)
    const int wn = warp_n * 64;
    const int m0 = blockIdx.y * BM;
    const int n0 = blockIdx.x * BN;
    const uint8_t* __restrict__ A = g_x_fp8;
    const uint8_t* __restrict__ B = g_w_fp8;
    const int NK = K / BK;               // 32

    // ldmatrix lane address components (derived from PTX fragment maps)
    const int la = lane & 15;                    // A: row-in-16
    const int lc = (lane >> 4) * 16;             // A: k-byte half
    const int br = (lane & 7) + ((lane & 16) >> 1);  // B: row-in-16
    const int bc = (lane & 8) ? 16 : 0;              // B: k-byte half

    // producer mapping: 256 rows-chunks per operand (128 rows x 2 16B pieces)
    const int prow = tid >> 1;
    const int pcc = (tid & 1) * 16;

    auto load_chunk = [&](int kt, int st) {
        uint32_t abase = sbase + (uint32_t)st * STB;
        uint32_t bbase = abase + OPB;
        uint32_t soff = (uint32_t)(prow * ROWB + pcc);
        cp_async16(abase + soff, A + (size_t)(m0 + prow) * K + kt * BK + pcc);
        cp_async16(bbase + soff, B + (size_t)(n0 + prow) * K + kt * BK + pcc);
    };

    float c[2][8][4];
#pragma unroll
    for (int i = 0; i < 2; i++)
#pragma unroll
        for (int j = 0; j < 8; j++)
#pragma unroll
            for (int q = 0; q < 4; q++) c[i][j][q] = 0.0f;

    // prologue: 3 chunks in flight
#pragma unroll
    for (int s = 0; s < STAGES - 1; s++) {
        load_chunk(s, s);
        cp_commit();
    }

    for (int i = 0; i < NK; i++) {
        cp_wait<STAGES - 2>();           // chunk i resident (i+1, i+2 in flight)
        __syncthreads();                 // everyone done reading buf (i+3)&3 (iter i-1)

        if (i + STAGES - 1 < NK) load_chunk(i + STAGES - 1, (i + STAGES - 1) & 3);
        cp_commit();                     // unconditional: keeps wait counts valid

        uint32_t abase = sbase + (uint32_t)(i & 3) * STB;
        uint32_t bbase = abase + OPB;

        // A fragments via ldmatrix.x4: r0..r3 = a0..a3 for ti block
        uint32_t af[2][4];
#pragma unroll
        for (int ti = 0; ti < 2; ti++)
            ldmatrix_x4(af[ti], abase + (uint32_t)((wm + 16 * ti + la) * ROWB) + lc);

        // B fragments: one x4 covers n-tiles 2j (r0,r1) and 2j+1 (r2,r3)
        uint32_t bf[4][4];
#pragma unroll
        for (int j = 0; j < 4; j++)
            ldmatrix_x4(bf[j], bbase + (uint32_t)((wn + 16 * j + br) * ROWB) + bc);

#pragma unroll
        for (int ti = 0; ti < 2; ti++)
#pragma unroll
            for (int j = 0; j < 4; j++) {
                mma_fp8(c[ti][2 * j],     af[ti], &bf[j][0]);
                mma_fp8(c[ti][2 * j + 1], af[ti], &bf[j][2]);
            }
    }

    // epilogue: f32 out, values rounded to bf16 grid (matches .astype(bf16))
    float act_scale = g_amax / FP8_MAX;
    const int row_b = m0 + wm + g;
    const int col_b = wn + 2 * t;
#pragma unroll
    for (int ti = 0; ti < 2; ti++) {
#pragma unroll
        for (int tj = 0; tj < 8; tj++) {
            int col = n0 + col_b + 8 * tj;
            float s0 = act_scale * __ldg(&wscale[col]);
            float s1 = act_scale * __ldg(&wscale[col + 1]);
            float b0 = __ldg(&bias[col]);
            float b1 = __ldg(&bias[col + 1]);
            int r0 = row_b + 16 * ti;
            int r1 = r0 + 8;
            float2 h0 = make_float2(bf16r(fmaf(c[ti][tj][0], s0, b0)),
                                    bf16r(fmaf(c[ti][tj][1], s1, b1)));
            float2 h1 = make_float2(bf16r(fmaf(c[ti][tj][2], s0, b0)),
                                    bf16r(fmaf(c[ti][tj][3], s1, b1)));
            *(float2*)(out + (size_t)r0 * N + col) = h0;
            *(float2*)(out + (size_t)r1 * N + col) = h1;
        }
    }
}

// ---------------- launch --------------------------------------------------------
extern "C" void kernel_launch(void* const* d_in, const int* in_sizes, int n_in,
                              void* d_out, int out_size) {
    const float* x  = (const float*)d_in[0];
    const float* w  = (const float*)d_in[1];
    const float* ws = (const float*)d_in[2];
    const float* b  = (const float*)d_in[3];
    float* out = (float*)d_out;                  // f32 container (numpy has no bf16)

    int d_out_dim = in_sizes[2];                 // 1024
    int d_in_dim  = in_sizes[1] / d_out_dim;     // 1024
    int tokens    = in_sizes[0] / d_in_dim;      // 32768
    int nx = in_sizes[0];
    int nw = in_sizes[1];

    k_amax1<<<1024, 256>>>(x, nx);
    k_amax2<<<1, 1024>>>();
    k_quant_x<<<2048, 256>>>(x, nx);
    k_quant_w<<<512, 256>>>(w, nw);

    dim3 grid(d_out_dim / BN, tokens / BM);      // N-tiles fastest -> A-tile L2 reuse
    k_gemm<<<grid, 256, SMEM_GEMM_TOTAL>>>(ws, b, out, tokens, d_out_dim, d_in_dim);
}

// round 9
// speedup vs baseline: 1.3639x; 1.1610x over previous
#include <cuda_runtime.h>
#include <cuda_bf16.h>
#include <cuda_fp8.h>
#include <cstdint>
#include <cstddef>

#define FP8_MAX 448.0f

// ---------------- scratch (device globals; no runtime allocation) -------------
static __device__ __align__(16) uint8_t g_x_fp8[(size_t)32768 * 1024];
static __device__ __align__(16) uint8_t g_w_fp8[(size_t)1024 * 1024];
static __device__ float g_part[1024];
static __device__ float g_amax;

__device__ __forceinline__ float bf16r(float v) {
    return __bfloat162float(__float2bfloat16(v));
}

// ---------------- PTX helpers -------------------------------------------------
__device__ __forceinline__ uint32_t smem_u32(const void* p) {
    uint32_t a;
    asm("{ .reg .u64 t; cvta.to.shared.u64 t, %1; cvt.u32.u64 %0, t; }"
        : "=r"(a) : "l"(p));
    return a;
}
__device__ __forceinline__ void cp_async16(uint32_t dst, const void* src) {
    asm volatile("cp.async.cg.shared.global [%0], [%1], 16;\n" :: "r"(dst), "l"(src));
}
__device__ __forceinline__ void cp_commit() {
    asm volatile("cp.async.commit_group;\n" ::: "memory");
}
template <int N>
__device__ __forceinline__ void cp_wait() {
    asm volatile("cp.async.wait_group %0;\n" :: "n"(N) : "memory");
}
__device__ __forceinline__ void ldmatrix_x4(uint32_t* r, uint32_t addr) {
    asm volatile("ldmatrix.sync.aligned.m8n8.x4.shared.b16 {%0,%1,%2,%3}, [%4];"
                 : "=r"(r[0]), "=r"(r[1]), "=r"(r[2]), "=r"(r[3]) : "r"(addr));
}
// fp8 e4m3 MMA: D(16x8,f32) += A(16x32,e4m3) * B(32x8,e4m3)
__device__ __forceinline__ void mma_fp8(float* c, const uint32_t* a, const uint32_t* b) {
    asm volatile(
        "mma.sync.aligned.m16n8k32.row.col.f32.e4m3.e4m3.f32 "
        "{%0,%1,%2,%3}, {%4,%5,%6,%7}, {%8,%9}, {%0,%1,%2,%3};"
        : "+f"(c[0]), "+f"(c[1]), "+f"(c[2]), "+f"(c[3])
        : "r"(a[0]), "r"(a[1]), "r"(a[2]), "r"(a[3]), "r"(b[0]), "r"(b[1]));
}

// ---------------- deterministic two-pass amax -----------------------------------
__global__ void k_amax1(const float* __restrict__ x, int n) {
    __shared__ float sm[256];
    float m0 = 0.0f, m1 = 0.0f;
    const float4* x4 = (const float4*)x;
    int n4 = n >> 2;
    int stride = gridDim.x * blockDim.x;
    for (int j = blockIdx.x * blockDim.x + threadIdx.x; j < n4; j += stride) {
        float4 v = x4[j];
        m0 = fmaxf(m0, fmaxf(fabsf(bf16r(v.x)), fabsf(bf16r(v.y))));
        m1 = fmaxf(m1, fmaxf(fabsf(bf16r(v.z)), fabsf(bf16r(v.w))));
    }
    sm[threadIdx.x] = fmaxf(m0, m1);
    __syncthreads();
#pragma unroll
    for (int o = 128; o > 0; o >>= 1) {
        if (threadIdx.x < o) sm[threadIdx.x] = fmaxf(sm[threadIdx.x], sm[threadIdx.x + o]);
        __syncthreads();
    }
    if (threadIdx.x == 0) g_part[blockIdx.x] = sm[0];
}
__global__ void k_amax2() {
    __shared__ float sm[1024];
    sm[threadIdx.x] = g_part[threadIdx.x];
    __syncthreads();
#pragma unroll
    for (int o = 512; o > 0; o >>= 1) {
        if (threadIdx.x < o) sm[threadIdx.x] = fmaxf(sm[threadIdx.x], sm[threadIdx.x + o]);
        __syncthreads();
    }
    if (threadIdx.x == 0) g_amax = fmaxf(sm[0], 1e-12f);
}

// ---------------- staging quant (x and w in one launch) --------------------------
__global__ void k_quant(const float* __restrict__ x, int nx4,
                        const float* __restrict__ w, int nw4) {
    float s = g_amax / FP8_MAX;
    int i = blockIdx.x * blockDim.x + threadIdx.x;
    int stride = gridDim.x * blockDim.x;
    const float4* x4 = (const float4*)x;
    uchar4* dx = (uchar4*)g_x_fp8;
    for (int j = i; j < nx4; j += stride) {
        float4 v = x4[j];
        uchar4 q;
        q.x = __nv_fp8_e4m3(bf16r(v.x) / s).__x;
        q.y = __nv_fp8_e4m3(bf16r(v.y) / s).__x;
        q.z = __nv_fp8_e4m3(bf16r(v.z) / s).__x;
        q.w = __nv_fp8_e4m3(bf16r(v.w) / s).__x;
        dx[j] = q;
    }
    const float4* w4 = (const float4*)w;
    uchar4* dw = (uchar4*)g_w_fp8;
    for (int j = i; j < nw4; j += stride) {
        float4 v = w4[j];
        uchar4 q;
        q.x = __nv_fp8_e4m3(v.x).__x;
        q.y = __nv_fp8_e4m3(v.y).__x;
        q.z = __nv_fp8_e4m3(v.z).__x;
        q.w = __nv_fp8_e4m3(v.w).__x;
        dw[j] = q;
    }
}

// ---------------- fp8 MMA GEMM (ldmatrix fragments, 4-stage cp.async) -----------
#define BM 128
#define BN 128
#define BK 32                            // 32 fp8 bytes of K per chunk
#define ROWB 48                          // 32 data bytes + 16 pad (16B aligned rows)
#define OPB (128 * ROWB)                 // 6144 per operand tile
#define STB (2 * OPB)                    // 12288 per stage
#define STAGES 4
#define SMEM_GEMM_TOTAL (STAGES * STB)   // 49152 == default 48KB limit

__global__ void __launch_bounds__(256, 2)   // force <=128 regs -> 2 CTAs/SM, 1 wave
k_gemm(const float* __restrict__ wscale,
       const float* __restrict__ bias,
       float* __restrict__ out,          // f32 container, bf16-rounded values
       int M, int N, int K)
{
    extern __shared__ __align__(128) uint8_t smem[];
    const uint32_t sbase = smem_u32(smem);
    const int tid = threadIdx.x;
    const int wid = tid >> 5;
    const int lane = tid & 31;
    const int g = lane >> 2;             // groupID
    const int t = lane & 3;              // threadID_in_group
    const int warp_m = wid & 3;          // 4 warps along M
    const int warp_n = wid >> 2;         // 2 warps along N
    const int wm = warp_m * 32;          // warp tile 32(M) x 64(N)
    const int wn = warp_n * 64;
    const int m0 = blockIdx.y * BM;
    const int n0 = blockIdx.x * BN;
    const uint8_t* __restrict__ A = g_x_fp8;
    const uint8_t* __restrict__ B = g_w_fp8;
    const int NK = K / BK;               // 32

    // ldmatrix lane address components (R8-validated)
    const int la = lane & 15;                        // A: row-in-16
    const int lc = (lane >> 4) * 16;                 // A: k-byte half
    const int br = (lane & 7) + ((lane & 16) >> 1);  // B: row-in-16
    const int bc = (lane & 8) ? 16 : 0;              // B: k-byte half

    // producer mapping: 128 rows x 2 16B pieces per operand
    const int prow = tid >> 1;
    const int pcc = (tid & 1) * 16;

    auto load_chunk = [&](int kt, int st) {
        uint32_t abase = sbase + (uint32_t)st * STB;
        uint32_t bbase = abase + OPB;
        uint32_t soff = (uint32_t)(prow * ROWB + pcc);
        cp_async16(abase + soff, A + (size_t)(m0 + prow) * K + kt * BK + pcc);
        cp_async16(bbase + soff, B + (size_t)(n0 + prow) * K + kt * BK + pcc);
    };

    float c[2][8][4];
#pragma unroll
    for (int i = 0; i < 2; i++)
#pragma unroll
        for (int j = 0; j < 8; j++)
#pragma unroll
            for (int q = 0; q < 4; q++) c[i][j][q] = 0.0f;

#pragma unroll
    for (int s = 0; s < STAGES - 1; s++) {
        load_chunk(s, s);
        cp_commit();
    }

    for (int i = 0; i < NK; i++) {
        cp_wait<STAGES - 2>();           // chunk i resident (i+1, i+2 in flight)
        __syncthreads();                 // all reads of buf (i+3)&3 finished

        if (i + STAGES - 1 < NK) load_chunk(i + STAGES - 1, (i + STAGES - 1) & 3);
        cp_commit();                     // unconditional: keeps wait counts valid

        uint32_t abase = sbase + (uint32_t)(i & 3) * STB;
        uint32_t bbase = abase + OPB;

        uint32_t af[2][4];
#pragma unroll
        for (int ti = 0; ti < 2; ti++)
            ldmatrix_x4(af[ti], abase + (uint32_t)((wm + 16 * ti + la) * ROWB) + lc);

        uint32_t bf[4][4];
#pragma unroll
        for (int j = 0; j < 4; j++)
            ldmatrix_x4(bf[j], bbase + (uint32_t)((wn + 16 * j + br) * ROWB) + bc);

#pragma unroll
        for (int ti = 0; ti < 2; ti++)
#pragma unroll
            for (int j = 0; j < 4; j++) {
                mma_fp8(c[ti][2 * j],     af[ti], &bf[j][0]);
                mma_fp8(c[ti][2 * j + 1], af[ti], &bf[j][2]);
            }
    }

    // epilogue: f32 out, values rounded to bf16 grid (matches .astype(bf16))
    float act_scale = g_amax / FP8_MAX;
    const int row_b = m0 + wm + g;
    const int col_b = wn + 2 * t;
#pragma unroll
    for (int ti = 0; ti < 2; ti++) {
#pragma unroll
        for (int tj = 0; tj < 8; tj++) {
            int col = n0 + col_b + 8 * tj;
            float s0 = act_scale * __ldg(&wscale[col]);
            float s1 = act_scale * __ldg(&wscale[col + 1]);
            float b0 = __ldg(&bias[col]);
            float b1 = __ldg(&bias[col + 1]);
            int r0 = row_b + 16 * ti;
            int r1 = r0 + 8;
            float2 h0 = make_float2(bf16r(fmaf(c[ti][tj][0], s0, b0)),
                                    bf16r(fmaf(c[ti][tj][1], s1, b1)));
            float2 h1 = make_float2(bf16r(fmaf(c[ti][tj][2], s0, b0)),
                                    bf16r(fmaf(c[ti][tj][3], s1, b1)));
            *(float2*)(out + (size_t)r0 * N + col) = h0;
            *(float2*)(out + (size_t)r1 * N + col) = h1;
        }
    }
}

// ---------------- launch --------------------------------------------------------
extern "C" void kernel_launch(void* const* d_in, const int* in_sizes, int n_in,
                              void* d_out, int out_size) {
    const float* x  = (const float*)d_in[0];
    const float* w  = (const float*)d_in[1];
    const float* ws = (const float*)d_in[2];
    const float* b  = (const float*)d_in[3];
    float* out = (float*)d_out;                  // f32 container (numpy has no bf16)

    int d_out_dim = in_sizes[2];                 // 1024
    int d_in_dim  = in_sizes[1] / d_out_dim;     // 1024
    int tokens    = in_sizes[0] / d_in_dim;      // 32768
    int nx = in_sizes[0];
    int nw = in_sizes[1];

    k_amax1<<<1024, 256>>>(x, nx);
    k_amax2<<<1, 1024>>>();
    k_quant<<<2048, 256>>>(x, nx >> 2, w, nw >> 2);

    dim3 grid(d_out_dim / BN, tokens / BM);      // N-tiles fastest -> A-tile L2 reuse
    k_gemm<<<grid, 256, SMEM_GEMM_TOTAL>>>(ws, b, out, tokens, d_out_dim, d_in_dim);
}